// round 1
// baseline (speedup 1.0000x reference)
#include <cuda_runtime.h>
#include <math.h>

#define MAXN 40000
#define MAXE 640000

// ---------------- static device scratch (no runtime allocation) ----------------
__device__ float g_q[MAXN * 128];
__device__ float g_k[MAXN * 128];
__device__ float g_v[MAXN * 128];
__device__ float g_rst[MAXN * 128];
__device__ float g_ffn[MAXN * 128];
__device__ float g_hbuf[MAXN * 512];
__device__ float g_scores[MAXE * 8];
__device__ int g_deg[MAXN];
__device__ int g_cursor[MAXN];
__device__ int g_rowptr[MAXN + 1];
__device__ int g_eidx[MAXE];

// ---------------- CSR build ----------------
__global__ void k_zero(int n) {
    int i = blockIdx.x * blockDim.x + threadIdx.x;
    if (i < n) { g_deg[i] = 0; g_cursor[i] = 0; }
}

__global__ void k_hist(const int* __restrict__ dst, int E) {
    int e = blockIdx.x * blockDim.x + threadIdx.x;
    if (e < E) atomicAdd(&g_deg[dst[e]], 1);
}

__global__ void k_scan(int n) {
    __shared__ int sh[1024];
    __shared__ int carry_s;
    int t = threadIdx.x;
    if (t == 0) carry_s = 0;
    __syncthreads();
    for (int base = 0; base < n; base += 1024) {
        int carry = carry_s;
        int v = (base + t < n) ? g_deg[base + t] : 0;
        sh[t] = v;
        __syncthreads();
        for (int off = 1; off < 1024; off <<= 1) {
            int x = (t >= off) ? sh[t - off] : 0;
            __syncthreads();
            sh[t] += x;
            __syncthreads();
        }
        if (base + t < n) g_rowptr[base + t + 1] = sh[t] + carry;
        if (t == 1023) carry_s = carry + sh[1023];
        __syncthreads();
    }
    if (t == 0) g_rowptr[0] = 0;
}

__global__ void k_fill(const int* __restrict__ dst, int E) {
    int e = blockIdx.x * blockDim.x + threadIdx.x;
    if (e < E) {
        int d = dst[e];
        int pos = atomicAdd(&g_cursor[d], 1);
        g_eidx[g_rowptr[d] + pos] = e;
    }
}

// ---------------- generic tiled fp32 GEMM: C = A(MxK) * B(KxNcol) [+bias][PReLU] ----------------
__global__ __launch_bounds__(256) void gemm_tiled(
    const float* __restrict__ A, const float* __restrict__ B, float* __restrict__ C,
    int M, int K, int Ncol,
    const float* __restrict__ bias, const float* __restrict__ prelu)
{
    __shared__ __align__(16) float As[32][68];  // [k][m], padded
    __shared__ __align__(16) float Bs[32][64];  // [k][n]

    int tid = threadIdx.x;
    int tx = tid & 15, ty = tid >> 4;
    int row0 = blockIdx.y * 64;
    int col0 = blockIdx.x * 64;

    float acc[4][4];
#pragma unroll
    for (int i = 0; i < 4; i++)
#pragma unroll
        for (int j = 0; j < 4; j++) acc[i][j] = 0.f;

    for (int k0 = 0; k0 < K; k0 += 32) {
        // A tile 64x32 -> transposed into As
        int ac = (tid & 7) * 4;
#pragma unroll
        for (int rr = 0; rr < 2; rr++) {
            int r = (tid >> 3) + rr * 32;
            int grow = row0 + r;
            float4 av = make_float4(0.f, 0.f, 0.f, 0.f);
            if (grow < M)
                av = *reinterpret_cast<const float4*>(&A[(long)grow * K + k0 + ac]);
            As[ac + 0][r] = av.x; As[ac + 1][r] = av.y;
            As[ac + 2][r] = av.z; As[ac + 3][r] = av.w;
        }
        // B tile 32x64
        int bc = (tid & 15) * 4;
#pragma unroll
        for (int rr = 0; rr < 2; rr++) {
            int r = (tid >> 4) + rr * 16;
            float4 bv = *reinterpret_cast<const float4*>(&B[(long)(k0 + r) * Ncol + col0 + bc]);
            *reinterpret_cast<float4*>(&Bs[r][bc]) = bv;
        }
        __syncthreads();
#pragma unroll
        for (int kk = 0; kk < 32; kk++) {
            float4 a4 = *reinterpret_cast<const float4*>(&As[kk][ty * 4]);
            float4 b4 = *reinterpret_cast<const float4*>(&Bs[kk][tx * 4]);
            float a[4] = {a4.x, a4.y, a4.z, a4.w};
            float b[4] = {b4.x, b4.y, b4.z, b4.w};
#pragma unroll
            for (int i = 0; i < 4; i++)
#pragma unroll
                for (int j = 0; j < 4; j++) acc[i][j] += a[i] * b[j];
        }
        __syncthreads();
    }

#pragma unroll
    for (int i = 0; i < 4; i++) {
        int r = row0 + ty * 4 + i;
        if (r >= M) break;
        float4 o;
        float* op = reinterpret_cast<float*>(&o);
#pragma unroll
        for (int j = 0; j < 4; j++) {
            int c = col0 + tx * 4 + j;
            float v = acc[i][j];
            if (bias) v += bias[c];
            if (prelu) v = (v >= 0.f) ? v : prelu[c] * v;
            op[j] = v;
        }
        *reinterpret_cast<float4*>(&C[(long)r * Ncol + col0 + tx * 4]) = o;
    }
}

// ---------------- attention + aggregate + residual + LN1, one block per dst node ----------------
__global__ __launch_bounds__(128) void k_attn(
    const int* __restrict__ src, const float* __restrict__ feat,
    const float* __restrict__ ln1g, const float* __restrict__ ln1b)
{
    int node = blockIdx.x;
    int tid = threadIdx.x, lane = tid & 31, warp = tid >> 5;

    __shared__ __align__(16) float q_sh[128];
    __shared__ float wmax[4][8], wsum[4][8];
    __shared__ float m_sh[8], inv_sh[8];
    __shared__ int s_src[256];
    __shared__ int s_eid[256];
    __shared__ float s_w[256 * 8];
    __shared__ float red4[4];

    int rs = g_rowptr[node], re = g_rowptr[node + 1];
    q_sh[tid] = g_q[node * 128 + tid];
    __syncthreads();

    // ---- phase 1: scores + per-head max (warp per edge) ----
    int h4 = lane >> 2;  // head owned by this lane group (4 lanes x float4 = 16 elems)
    float lmax = -INFINITY;
    float4 q4 = *reinterpret_cast<const float4*>(&q_sh[lane * 4]);
    for (int j = rs + warp; j < re; j += 4) {
        int e = g_eidx[j];
        int s = src[e];
        float4 k4 = *reinterpret_cast<const float4*>(&g_k[(long)s * 128 + lane * 4]);
        float p = k4.x * q4.x + k4.y * q4.y + k4.z * q4.z + k4.w * q4.w;
        p += __shfl_xor_sync(0xffffffffu, p, 1);
        p += __shfl_xor_sync(0xffffffffu, p, 2);
        float sv = p * 0.08838834764831845f;  // 1/sqrt(128)
        if ((lane & 3) == 0) g_scores[(long)e * 8 + h4] = sv;
        lmax = fmaxf(lmax, sv);
    }
    if ((lane & 3) == 0) wmax[warp][h4] = lmax;
    __syncthreads();
    if (tid < 8)
        m_sh[tid] = fmaxf(fmaxf(wmax[0][tid], wmax[1][tid]),
                          fmaxf(wmax[2][tid], wmax[3][tid]));
    __syncthreads();

    // ---- phase 2: exp + per-head sum ----
    float lsum = 0.f;
    float mh = (lane < 8) ? m_sh[lane] : 0.f;
    for (int j = rs + warp; j < re; j += 4) {
        int e = g_eidx[j];
        if (lane < 8) {
            float sv = g_scores[(long)e * 8 + lane];
            float ex = __expf(sv - mh);
            g_scores[(long)e * 8 + lane] = ex;
            lsum += ex;
        }
    }
    if (lane < 8) wsum[warp][lane] = lsum;
    __syncthreads();
    if (tid < 8) {
        float t = wsum[0][tid] + wsum[1][tid] + wsum[2][tid] + wsum[3][tid];
        inv_sh[tid] = (t > 0.f) ? (1.f / t) : 0.f;
    }
    __syncthreads();

    // ---- phase 3: weighted aggregation of v[src], channel-parallel ----
    float acc = 0.f;
    int h = tid >> 4;
    for (int base = rs; base < re; base += 256) {
        int cnt = min(256, re - base);
        for (int jj = tid; jj < cnt; jj += 128) {
            int e = g_eidx[base + jj];
            s_eid[jj] = e;
            s_src[jj] = src[e];
        }
        __syncthreads();
        for (int idx = tid; idx < cnt * 8; idx += 128) {
            int jj = idx >> 3, hh = idx & 7;
            s_w[idx] = g_scores[(long)s_eid[jj] * 8 + hh] * inv_sh[hh];
        }
        __syncthreads();
        int jj = 0;
        for (; jj + 4 <= cnt; jj += 4) {
            float v0 = g_v[(long)s_src[jj + 0] * 128 + tid];
            float v1 = g_v[(long)s_src[jj + 1] * 128 + tid];
            float v2 = g_v[(long)s_src[jj + 2] * 128 + tid];
            float v3 = g_v[(long)s_src[jj + 3] * 128 + tid];
            acc += v0 * s_w[(jj + 0) * 8 + h];
            acc += v1 * s_w[(jj + 1) * 8 + h];
            acc += v2 * s_w[(jj + 2) * 8 + h];
            acc += v3 * s_w[(jj + 3) * 8 + h];
        }
        for (; jj < cnt; jj++)
            acc += g_v[(long)s_src[jj] * 128 + tid] * s_w[jj * 8 + h];
        __syncthreads();
    }

    // ---- phase 4: residual + LayerNorm1 ----
    float x = acc + feat[(long)node * 128 + tid];
    float ssum = x;
#pragma unroll
    for (int o = 16; o >= 1; o >>= 1) ssum += __shfl_xor_sync(0xffffffffu, ssum, o);
    if (lane == 0) red4[warp] = ssum;
    __syncthreads();
    float mu = (red4[0] + red4[1] + red4[2] + red4[3]) * (1.f / 128.f);
    __syncthreads();
    float d = x - mu;
    float vv = d * d;
#pragma unroll
    for (int o = 16; o >= 1; o >>= 1) vv += __shfl_xor_sync(0xffffffffu, vv, o);
    if (lane == 0) red4[warp] = vv;
    __syncthreads();
    float var = (red4[0] + red4[1] + red4[2] + red4[3]) * (1.f / 128.f);
    float y = d * rsqrtf(var + 1e-5f) * ln1g[tid] + ln1b[tid];
    g_rst[(long)node * 128 + tid] = y;
}

// ---------------- residual + LayerNorm2 -> output ----------------
__global__ __launch_bounds__(128) void k_ln2(
    const float* __restrict__ ln2g, const float* __restrict__ ln2b,
    float* __restrict__ out)
{
    int node = blockIdx.x;
    int tid = threadIdx.x, lane = tid & 31, warp = tid >> 5;
    __shared__ float red4[4];

    float x = g_rst[(long)node * 128 + tid] + g_ffn[(long)node * 128 + tid];
    float ssum = x;
#pragma unroll
    for (int o = 16; o >= 1; o >>= 1) ssum += __shfl_xor_sync(0xffffffffu, ssum, o);
    if (lane == 0) red4[warp] = ssum;
    __syncthreads();
    float mu = (red4[0] + red4[1] + red4[2] + red4[3]) * (1.f / 128.f);
    __syncthreads();
    float d = x - mu;
    float vv = d * d;
#pragma unroll
    for (int o = 16; o >= 1; o >>= 1) vv += __shfl_xor_sync(0xffffffffu, vv, o);
    if (lane == 0) red4[warp] = vv;
    __syncthreads();
    float var = (red4[0] + red4[1] + red4[2] + red4[3]) * (1.f / 128.f);
    out[(long)node * 128 + tid] = d * rsqrtf(var + 1e-5f) * ln2g[tid] + ln2b[tid];
}

// ---------------- launch ----------------
extern "C" void kernel_launch(void* const* d_in, const int* in_sizes, int n_in,
                              void* d_out, int out_size)
{
    const float* feat  = (const float*)d_in[0];
    const int*   src   = (const int*)d_in[1];
    const int*   dst   = (const int*)d_in[2];
    const float* Wq    = (const float*)d_in[3];
    const float* Wk    = (const float*)d_in[4];
    const float* Wv    = (const float*)d_in[5];
    const float* ln1g  = (const float*)d_in[6];
    const float* ln1b  = (const float*)d_in[7];
    const float* ln2g  = (const float*)d_in[8];
    const float* ln2b  = (const float*)d_in[9];
    const float* W1    = (const float*)d_in[10];
    const float* b1    = (const float*)d_in[11];
    const float* prelu = (const float*)d_in[12];
    const float* W2    = (const float*)d_in[13];
    const float* b2    = (const float*)d_in[14];
    float* out = (float*)d_out;

    int N = in_sizes[0] / 128;
    int E = in_sizes[1];

    float *qp, *kp, *vp, *rstp, *ffnp, *hp;
    cudaGetSymbolAddress((void**)&qp, g_q);
    cudaGetSymbolAddress((void**)&kp, g_k);
    cudaGetSymbolAddress((void**)&vp, g_v);
    cudaGetSymbolAddress((void**)&rstp, g_rst);
    cudaGetSymbolAddress((void**)&ffnp, g_ffn);
    cudaGetSymbolAddress((void**)&hp, g_hbuf);

    // CSR build
    k_zero<<<(N + 255) / 256, 256>>>(N);
    k_hist<<<(E + 255) / 256, 256>>>(dst, E);
    k_scan<<<1, 1024>>>(N);
    k_fill<<<(E + 255) / 256, 256>>>(dst, E);

    // QKV projections
    dim3 gqkv(128 / 64, (N + 63) / 64);
    gemm_tiled<<<gqkv, 256>>>(feat, Wq, qp, N, 128, 128, nullptr, nullptr);
    gemm_tiled<<<gqkv, 256>>>(feat, Wk, kp, N, 128, 128, nullptr, nullptr);
    gemm_tiled<<<gqkv, 256>>>(feat, Wv, vp, N, 128, 128, nullptr, nullptr);

    // attention + aggregate + residual + LN1
    k_attn<<<N, 128>>>(src, feat, ln1g, ln1b);

    // FFN
    dim3 gff1(512 / 64, (N + 63) / 64);
    gemm_tiled<<<gff1, 256>>>(rstp, W1, hp, N, 128, 512, b1, prelu);
    dim3 gff2(128 / 64, (N + 63) / 64);
    gemm_tiled<<<gff2, 256>>>(hp, W2, ffnp, N, 512, 128, b2, nullptr);

    // residual + LN2 -> out
    k_ln2<<<N, 128>>>(ln2g, ln2b, out);
}

// round 2
// speedup vs baseline: 1.1971x; 1.1971x over previous
#include <cuda_runtime.h>
#include <math.h>

#define MAXN 40000
#define MAXE 640000

// ---------------- static device scratch (no runtime allocation) ----------------
__device__ float g_q[MAXN * 128];
__device__ float g_k[MAXN * 128];
__device__ float g_v[MAXN * 128];
__device__ float g_rst[MAXN * 128];
__device__ float g_ffn[MAXN * 128];
__device__ float g_hbuf[MAXN * 512];
__device__ float g_scores[MAXE * 8];
__device__ int g_deg[MAXN];
__device__ int g_cursor[MAXN];
__device__ int g_rowptr[MAXN + 1];
__device__ int g_eidx[MAXE];

// ---------------- CSR build ----------------
__global__ void k_zero(int n) {
    int i = blockIdx.x * blockDim.x + threadIdx.x;
    if (i < n) { g_deg[i] = 0; g_cursor[i] = 0; }
}

__global__ void k_hist(const int* __restrict__ dst, int E) {
    int e = blockIdx.x * blockDim.x + threadIdx.x;
    if (e < E) atomicAdd(&g_deg[dst[e]], 1);
}

__global__ void k_scan(int n) {
    __shared__ int sh[1024];
    __shared__ int carry_s;
    int t = threadIdx.x;
    if (t == 0) carry_s = 0;
    __syncthreads();
    for (int base = 0; base < n; base += 1024) {
        int carry = carry_s;
        int v = (base + t < n) ? g_deg[base + t] : 0;
        sh[t] = v;
        __syncthreads();
        for (int off = 1; off < 1024; off <<= 1) {
            int x = (t >= off) ? sh[t - off] : 0;
            __syncthreads();
            sh[t] += x;
            __syncthreads();
        }
        if (base + t < n) g_rowptr[base + t + 1] = sh[t] + carry;
        if (t == 1023) carry_s = carry + sh[1023];
        __syncthreads();
    }
    if (t == 0) g_rowptr[0] = 0;
}

__global__ void k_fill(const int* __restrict__ dst, int E) {
    int e = blockIdx.x * blockDim.x + threadIdx.x;
    if (e < E) {
        int d = dst[e];
        int pos = atomicAdd(&g_cursor[d], 1);
        g_eidx[g_rowptr[d] + pos] = e;
    }
}

// ---------------- tf32 tensor-core GEMM ----------------
__device__ __forceinline__ unsigned f2tf32(float x) {
    unsigned r;
    asm("cvt.rna.tf32.f32 %0, %1;" : "=r"(r) : "f"(x));
    return r;
}

__device__ __forceinline__ void mma_tf32(float* c, const unsigned* a, const unsigned* b) {
    asm volatile(
        "mma.sync.aligned.m16n8k8.row.col.f32.tf32.tf32.f32 "
        "{%0,%1,%2,%3}, {%4,%5,%6,%7}, {%8,%9}, {%0,%1,%2,%3};\n"
        : "+f"(c[0]), "+f"(c[1]), "+f"(c[2]), "+f"(c[3])
        : "r"(a[0]), "r"(a[1]), "r"(a[2]), "r"(a[3]), "r"(b[0]), "r"(b[1]));
}

// C = A(MxK) * B(KxNcol) [+bias][PReLU], BM=128 BN=128 BK=32, 256 threads.
// K, Ncol multiples of 32/128; M may have a tail.
__global__ __launch_bounds__(256) void gemm_tf32(
    const float* __restrict__ A, const float* __restrict__ B, float* __restrict__ C,
    int M, int K, int Ncol,
    const float* __restrict__ bias, const float* __restrict__ prelu)
{
    const int BM = 128, BN = 128, BK = 32;
    __shared__ unsigned As[BK][BM + 8];
    __shared__ unsigned Bs[BK][BN + 8];

    int tid = threadIdx.x, lane = tid & 31, warp = tid >> 5;
    int wm = warp & 1, wn = warp >> 1;             // 2 x 4 warp grid
    int row0 = blockIdx.y * BM, col0 = blockIdx.x * BN;
    int g = lane >> 2, tg = lane & 3;

    float acc[4][4][4];
#pragma unroll
    for (int mt = 0; mt < 4; mt++)
#pragma unroll
        for (int nt = 0; nt < 4; nt++)
#pragma unroll
            for (int r = 0; r < 4; r++) acc[mt][nt][r] = 0.f;

    // A-tile load mapping: each thread owns one row, 16 consecutive k's
    int arow = tid >> 1;
    int akc = (tid & 1) * 16;
    // B-tile load mapping: each thread owns one k-row, 16 consecutive n's
    int bkr = tid >> 3;
    int bnc = (tid & 7) * 16;

    for (int k0 = 0; k0 < K; k0 += BK) {
        // ---- load + transpose A tile (with M-tail guard) ----
        {
            int grow = row0 + arow;
            if (grow < M) {
                const float* ap = &A[(long)grow * K + k0 + akc];
#pragma unroll
                for (int q4 = 0; q4 < 4; q4++) {
                    float4 v = *reinterpret_cast<const float4*>(ap + q4 * 4);
                    As[akc + q4 * 4 + 0][arow] = f2tf32(v.x);
                    As[akc + q4 * 4 + 1][arow] = f2tf32(v.y);
                    As[akc + q4 * 4 + 2][arow] = f2tf32(v.z);
                    As[akc + q4 * 4 + 3][arow] = f2tf32(v.w);
                }
            } else {
#pragma unroll
                for (int q = 0; q < 16; q++) As[akc + q][arow] = 0u;
            }
        }
        // ---- load B tile ----
        {
            const float* bp = &B[(long)(k0 + bkr) * Ncol + col0 + bnc];
#pragma unroll
            for (int q4 = 0; q4 < 4; q4++) {
                float4 v = *reinterpret_cast<const float4*>(bp + q4 * 4);
                Bs[bkr][bnc + q4 * 4 + 0] = f2tf32(v.x);
                Bs[bkr][bnc + q4 * 4 + 1] = f2tf32(v.y);
                Bs[bkr][bnc + q4 * 4 + 2] = f2tf32(v.z);
                Bs[bkr][bnc + q4 * 4 + 3] = f2tf32(v.w);
            }
        }
        __syncthreads();

#pragma unroll
        for (int kk = 0; kk < BK; kk += 8) {
            unsigned af[4][4];
#pragma unroll
            for (int mt = 0; mt < 4; mt++) {
                int mb = wm * 64 + mt * 16;
                af[mt][0] = As[kk + tg][mb + g];
                af[mt][1] = As[kk + tg][mb + g + 8];
                af[mt][2] = As[kk + tg + 4][mb + g];
                af[mt][3] = As[kk + tg + 4][mb + g + 8];
            }
            unsigned bf[4][2];
#pragma unroll
            for (int nt = 0; nt < 4; nt++) {
                int nb = wn * 32 + nt * 8;
                bf[nt][0] = Bs[kk + tg][nb + g];
                bf[nt][1] = Bs[kk + tg + 4][nb + g];
            }
#pragma unroll
            for (int mt = 0; mt < 4; mt++)
#pragma unroll
                for (int nt = 0; nt < 4; nt++)
                    mma_tf32(acc[mt][nt], af[mt], bf[nt]);
        }
        __syncthreads();
    }

    // ---- epilogue ----
#pragma unroll
    for (int mt = 0; mt < 4; mt++) {
        int rbase = row0 + wm * 64 + mt * 16 + g;
#pragma unroll
        for (int nt = 0; nt < 4; nt++) {
            int cbase = col0 + wn * 32 + nt * 8 + 2 * tg;
#pragma unroll
            for (int half = 0; half < 2; half++) {
                int r = rbase + half * 8;
                if (r >= M) continue;
#pragma unroll
                for (int jj = 0; jj < 2; jj++) {
                    int c = cbase + jj;
                    float v = acc[mt][nt][half * 2 + jj];
                    if (bias) v += bias[c];
                    if (prelu) v = (v >= 0.f) ? v : prelu[c] * v;
                    C[(long)r * Ncol + c] = v;
                }
            }
        }
    }
}

// ---------------- attention + aggregate + residual + LN1, one block per dst node ----------------
__global__ __launch_bounds__(128) void k_attn(
    const int* __restrict__ src, const float* __restrict__ feat,
    const float* __restrict__ ln1g, const float* __restrict__ ln1b)
{
    int node = blockIdx.x;
    int tid = threadIdx.x, lane = tid & 31, warp = tid >> 5;

    __shared__ __align__(16) float q_sh[128];
    __shared__ float wmax[4][8], wsum[4][8];
    __shared__ float m_sh[8], inv_sh[8];
    __shared__ int s_src[256];
    __shared__ int s_eid[256];
    __shared__ float s_w[256 * 8];
    __shared__ float red4[4];

    int rs = g_rowptr[node], re = g_rowptr[node + 1];
    q_sh[tid] = g_q[node * 128 + tid];
    __syncthreads();

    // ---- phase 1: scores + per-head max (warp per edge) ----
    int h4 = lane >> 2;
    float lmax = -INFINITY;
    float4 q4 = *reinterpret_cast<const float4*>(&q_sh[lane * 4]);
    for (int j = rs + warp; j < re; j += 4) {
        int e = g_eidx[j];
        int s = src[e];
        float4 k4 = *reinterpret_cast<const float4*>(&g_k[(long)s * 128 + lane * 4]);
        float p = k4.x * q4.x + k4.y * q4.y + k4.z * q4.z + k4.w * q4.w;
        p += __shfl_xor_sync(0xffffffffu, p, 1);
        p += __shfl_xor_sync(0xffffffffu, p, 2);
        float sv = p * 0.08838834764831845f;  // 1/sqrt(128)
        if ((lane & 3) == 0) g_scores[(long)e * 8 + h4] = sv;
        lmax = fmaxf(lmax, sv);
    }
    if ((lane & 3) == 0) wmax[warp][h4] = lmax;
    __syncthreads();
    if (tid < 8)
        m_sh[tid] = fmaxf(fmaxf(wmax[0][tid], wmax[1][tid]),
                          fmaxf(wmax[2][tid], wmax[3][tid]));
    __syncthreads();

    // ---- phase 2: exp + per-head sum ----
    float lsum = 0.f;
    float mh = (lane < 8) ? m_sh[lane] : 0.f;
    for (int j = rs + warp; j < re; j += 4) {
        int e = g_eidx[j];
        if (lane < 8) {
            float sv = g_scores[(long)e * 8 + lane];
            float ex = __expf(sv - mh);
            g_scores[(long)e * 8 + lane] = ex;
            lsum += ex;
        }
    }
    if (lane < 8) wsum[warp][lane] = lsum;
    __syncthreads();
    if (tid < 8) {
        float t = wsum[0][tid] + wsum[1][tid] + wsum[2][tid] + wsum[3][tid];
        inv_sh[tid] = (t > 0.f) ? (1.f / t) : 0.f;
    }
    __syncthreads();

    // ---- phase 3: weighted aggregation of v[src], channel-parallel ----
    float acc = 0.f;
    int h = tid >> 4;
    for (int base = rs; base < re; base += 256) {
        int cnt = min(256, re - base);
        for (int jj = tid; jj < cnt; jj += 128) {
            int e = g_eidx[base + jj];
            s_eid[jj] = e;
            s_src[jj] = src[e];
        }
        __syncthreads();
        for (int idx = tid; idx < cnt * 8; idx += 128) {
            int jj = idx >> 3, hh = idx & 7;
            s_w[idx] = g_scores[(long)s_eid[jj] * 8 + hh] * inv_sh[hh];
        }
        __syncthreads();
        int jj = 0;
        for (; jj + 4 <= cnt; jj += 4) {
            float v0 = g_v[(long)s_src[jj + 0] * 128 + tid];
            float v1 = g_v[(long)s_src[jj + 1] * 128 + tid];
            float v2 = g_v[(long)s_src[jj + 2] * 128 + tid];
            float v3 = g_v[(long)s_src[jj + 3] * 128 + tid];
            acc += v0 * s_w[(jj + 0) * 8 + h];
            acc += v1 * s_w[(jj + 1) * 8 + h];
            acc += v2 * s_w[(jj + 2) * 8 + h];
            acc += v3 * s_w[(jj + 3) * 8 + h];
        }
        for (; jj < cnt; jj++)
            acc += g_v[(long)s_src[jj] * 128 + tid] * s_w[jj * 8 + h];
        __syncthreads();
    }

    // ---- phase 4: residual + LayerNorm1 ----
    float x = acc + feat[(long)node * 128 + tid];
    float ssum = x;
#pragma unroll
    for (int o = 16; o >= 1; o >>= 1) ssum += __shfl_xor_sync(0xffffffffu, ssum, o);
    if (lane == 0) red4[warp] = ssum;
    __syncthreads();
    float mu = (red4[0] + red4[1] + red4[2] + red4[3]) * (1.f / 128.f);
    __syncthreads();
    float d = x - mu;
    float vv = d * d;
#pragma unroll
    for (int o = 16; o >= 1; o >>= 1) vv += __shfl_xor_sync(0xffffffffu, vv, o);
    if (lane == 0) red4[warp] = vv;
    __syncthreads();
    float var = (red4[0] + red4[1] + red4[2] + red4[3]) * (1.f / 128.f);
    float y = d * rsqrtf(var + 1e-5f) * ln1g[tid] + ln1b[tid];
    g_rst[(long)node * 128 + tid] = y;
}

// ---------------- residual + LayerNorm2 -> output ----------------
__global__ __launch_bounds__(128) void k_ln2(
    const float* __restrict__ ln2g, const float* __restrict__ ln2b,
    float* __restrict__ out)
{
    int node = blockIdx.x;
    int tid = threadIdx.x, lane = tid & 31, warp = tid >> 5;
    __shared__ float red4[4];

    float x = g_rst[(long)node * 128 + tid] + g_ffn[(long)node * 128 + tid];
    float ssum = x;
#pragma unroll
    for (int o = 16; o >= 1; o >>= 1) ssum += __shfl_xor_sync(0xffffffffu, ssum, o);
    if (lane == 0) red4[warp] = ssum;
    __syncthreads();
    float mu = (red4[0] + red4[1] + red4[2] + red4[3]) * (1.f / 128.f);
    __syncthreads();
    float d = x - mu;
    float vv = d * d;
#pragma unroll
    for (int o = 16; o >= 1; o >>= 1) vv += __shfl_xor_sync(0xffffffffu, vv, o);
    if (lane == 0) red4[warp] = vv;
    __syncthreads();
    float var = (red4[0] + red4[1] + red4[2] + red4[3]) * (1.f / 128.f);
    out[(long)node * 128 + tid] = d * rsqrtf(var + 1e-5f) * ln2g[tid] + ln2b[tid];
}

// ---------------- launch ----------------
extern "C" void kernel_launch(void* const* d_in, const int* in_sizes, int n_in,
                              void* d_out, int out_size)
{
    const float* feat  = (const float*)d_in[0];
    const int*   src   = (const int*)d_in[1];
    const int*   dst   = (const int*)d_in[2];
    const float* Wq    = (const float*)d_in[3];
    const float* Wk    = (const float*)d_in[4];
    const float* Wv    = (const float*)d_in[5];
    const float* ln1g  = (const float*)d_in[6];
    const float* ln1b  = (const float*)d_in[7];
    const float* ln2g  = (const float*)d_in[8];
    const float* ln2b  = (const float*)d_in[9];
    const float* W1    = (const float*)d_in[10];
    const float* b1    = (const float*)d_in[11];
    const float* prelu = (const float*)d_in[12];
    const float* W2    = (const float*)d_in[13];
    const float* b2    = (const float*)d_in[14];
    float* out = (float*)d_out;

    int N = in_sizes[0] / 128;
    int E = in_sizes[1];

    float *qp, *kp, *vp, *rstp, *ffnp, *hp;
    cudaGetSymbolAddress((void**)&qp, g_q);
    cudaGetSymbolAddress((void**)&kp, g_k);
    cudaGetSymbolAddress((void**)&vp, g_v);
    cudaGetSymbolAddress((void**)&rstp, g_rst);
    cudaGetSymbolAddress((void**)&ffnp, g_ffn);
    cudaGetSymbolAddress((void**)&hp, g_hbuf);

    // CSR build
    k_zero<<<(N + 255) / 256, 256>>>(N);
    k_hist<<<(E + 255) / 256, 256>>>(dst, E);
    k_scan<<<1, 1024>>>(N);
    k_fill<<<(E + 255) / 256, 256>>>(dst, E);

    int mblk = (N + 127) / 128;

    // QKV projections (tf32 tensor cores)
    dim3 gqkv(1, mblk);
    gemm_tf32<<<gqkv, 256>>>(feat, Wq, qp, N, 128, 128, nullptr, nullptr);
    gemm_tf32<<<gqkv, 256>>>(feat, Wk, kp, N, 128, 128, nullptr, nullptr);
    gemm_tf32<<<gqkv, 256>>>(feat, Wv, vp, N, 128, 128, nullptr, nullptr);

    // attention + aggregate + residual + LN1
    k_attn<<<N, 128>>>(src, feat, ln1g, ln1b);

    // FFN (tf32 tensor cores)
    dim3 gff1(4, mblk);
    gemm_tf32<<<gff1, 256>>>(rstp, W1, hp, N, 128, 512, b1, prelu);
    dim3 gff2(1, mblk);
    gemm_tf32<<<gff2, 256>>>(hp, W2, ffnp, N, 512, 128, b2, nullptr);

    // residual + LN2 -> out
    k_ln2<<<N, 128>>>(ln2g, ln2b, out);
}

// round 3
// speedup vs baseline: 1.4583x; 1.2182x over previous
#include <cuda_runtime.h>
#include <math.h>

#define MAXN 40000
#define MAXE 640000

// ---------------- static device scratch ----------------
__device__ float g_q[MAXN * 128];
__device__ float g_k[MAXN * 128];
__device__ float g_v[MAXN * 128];
__device__ float g_rst[MAXN * 128];
__device__ float g_ffn[MAXN * 128];
__device__ float g_hbuf[MAXN * 512];
__device__ float g_scores[MAXE * 8];   // slow path only
__device__ int g_deg[MAXN];
__device__ int g_cursor[MAXN];
__device__ int g_rowptr[MAXN + 1];
__device__ int g_esrc[MAXE];           // src node per CSR slot

// ---------------- CSR build ----------------
__global__ void k_zero(int n) {
    int i = blockIdx.x * blockDim.x + threadIdx.x;
    if (i < n) { g_deg[i] = 0; g_cursor[i] = 0; }
}

__global__ void k_hist(const int* __restrict__ dst, int E) {
    int e = blockIdx.x * blockDim.x + threadIdx.x;
    if (e < E) atomicAdd(&g_deg[dst[e]], 1);
}

__global__ void k_scan(int n) {
    __shared__ int sh[1024];
    __shared__ int carry_s;
    int t = threadIdx.x;
    if (t == 0) carry_s = 0;
    __syncthreads();
    for (int base = 0; base < n; base += 1024) {
        int carry = carry_s;
        int v = (base + t < n) ? g_deg[base + t] : 0;
        sh[t] = v;
        __syncthreads();
        for (int off = 1; off < 1024; off <<= 1) {
            int x = (t >= off) ? sh[t - off] : 0;
            __syncthreads();
            sh[t] += x;
            __syncthreads();
        }
        if (base + t < n) g_rowptr[base + t + 1] = sh[t] + carry;
        if (t == 1023) carry_s = carry + sh[1023];
        __syncthreads();
    }
    if (t == 0) g_rowptr[0] = 0;
}

__global__ void k_fill(const int* __restrict__ dst, const int* __restrict__ src, int E) {
    int e = blockIdx.x * blockDim.x + threadIdx.x;
    if (e < E) {
        int d = dst[e];
        int pos = atomicAdd(&g_cursor[d], 1);
        g_esrc[g_rowptr[d] + pos] = src[e];
    }
}

// ---------------- tf32 tensor-core GEMM core ----------------
__device__ __forceinline__ unsigned f2tf32(float x) {
    unsigned r;
    asm("cvt.rna.tf32.f32 %0, %1;" : "=r"(r) : "f"(x));
    return r;
}

__device__ __forceinline__ void mma_tf32(float* c, const unsigned* a, const unsigned* b) {
    asm volatile(
        "mma.sync.aligned.m16n8k8.row.col.f32.tf32.tf32.f32 "
        "{%0,%1,%2,%3}, {%4,%5,%6,%7}, {%8,%9}, {%0,%1,%2,%3};\n"
        : "+f"(c[0]), "+f"(c[1]), "+f"(c[2]), "+f"(c[3])
        : "r"(a[0]), "r"(a[1]), "r"(a[2]), "r"(a[3]), "r"(b[0]), "r"(b[1]));
}

// 128x128x32 tile, 256 threads, register-prefetch double buffering.
__device__ __forceinline__ void gemm_body(
    const float* __restrict__ A, const float* __restrict__ B, float* __restrict__ C,
    int M, int K, int Ncol, int row0, int col0,
    const float* __restrict__ bias, const float* __restrict__ prelu)
{
    const int BM = 128, BN = 128, BK = 32;
    __shared__ unsigned As[BK][BM + 8];
    __shared__ unsigned Bs[BK][BN + 8];

    int tid = threadIdx.x, lane = tid & 31, warp = tid >> 5;
    int wm = warp & 1, wn = warp >> 1;
    int g = lane >> 2, tg = lane & 3;

    float acc[4][4][4];
#pragma unroll
    for (int mt = 0; mt < 4; mt++)
#pragma unroll
        for (int nt = 0; nt < 4; nt++)
#pragma unroll
            for (int r = 0; r < 4; r++) acc[mt][nt][r] = 0.f;

    int arow = tid >> 1;
    int akc = (tid & 1) * 16;
    int bkr = tid >> 3;
    int bnc = (tid & 7) * 16;

    float a_reg[16], b_reg[16];

    // prefetch first tile
    {
        int grow = row0 + arow;
        if (grow < M) {
            const float* ap = &A[(long)grow * K + akc];
#pragma unroll
            for (int q4 = 0; q4 < 4; q4++) {
                float4 v = *reinterpret_cast<const float4*>(ap + q4 * 4);
                a_reg[q4 * 4 + 0] = v.x; a_reg[q4 * 4 + 1] = v.y;
                a_reg[q4 * 4 + 2] = v.z; a_reg[q4 * 4 + 3] = v.w;
            }
        } else {
#pragma unroll
            for (int q = 0; q < 16; q++) a_reg[q] = 0.f;
        }
        const float* bp = &B[(long)bkr * Ncol + col0 + bnc];
#pragma unroll
        for (int q4 = 0; q4 < 4; q4++) {
            float4 v = *reinterpret_cast<const float4*>(bp + q4 * 4);
            b_reg[q4 * 4 + 0] = v.x; b_reg[q4 * 4 + 1] = v.y;
            b_reg[q4 * 4 + 2] = v.z; b_reg[q4 * 4 + 3] = v.w;
        }
    }

    for (int k0 = 0; k0 < K; k0 += BK) {
        // store current tile to smem (tf32-converted)
#pragma unroll
        for (int q = 0; q < 16; q++) As[akc + q][arow] = f2tf32(a_reg[q]);
#pragma unroll
        for (int q = 0; q < 16; q++) Bs[bkr][bnc + q] = f2tf32(b_reg[q]);
        __syncthreads();

        // prefetch next tile (overlaps with MMA below)
        if (k0 + BK < K) {
            int grow = row0 + arow;
            if (grow < M) {
                const float* ap = &A[(long)grow * K + k0 + BK + akc];
#pragma unroll
                for (int q4 = 0; q4 < 4; q4++) {
                    float4 v = *reinterpret_cast<const float4*>(ap + q4 * 4);
                    a_reg[q4 * 4 + 0] = v.x; a_reg[q4 * 4 + 1] = v.y;
                    a_reg[q4 * 4 + 2] = v.z; a_reg[q4 * 4 + 3] = v.w;
                }
            }
            const float* bp = &B[(long)(k0 + BK + bkr) * Ncol + col0 + bnc];
#pragma unroll
            for (int q4 = 0; q4 < 4; q4++) {
                float4 v = *reinterpret_cast<const float4*>(bp + q4 * 4);
                b_reg[q4 * 4 + 0] = v.x; b_reg[q4 * 4 + 1] = v.y;
                b_reg[q4 * 4 + 2] = v.z; b_reg[q4 * 4 + 3] = v.w;
            }
        }

#pragma unroll
        for (int kk = 0; kk < BK; kk += 8) {
            unsigned af[4][4];
#pragma unroll
            for (int mt = 0; mt < 4; mt++) {
                int mb = wm * 64 + mt * 16;
                af[mt][0] = As[kk + tg][mb + g];
                af[mt][1] = As[kk + tg][mb + g + 8];
                af[mt][2] = As[kk + tg + 4][mb + g];
                af[mt][3] = As[kk + tg + 4][mb + g + 8];
            }
            unsigned bf[4][2];
#pragma unroll
            for (int nt = 0; nt < 4; nt++) {
                int nb = wn * 32 + nt * 8;
                bf[nt][0] = Bs[kk + tg][nb + g];
                bf[nt][1] = Bs[kk + tg + 4][nb + g];
            }
#pragma unroll
            for (int mt = 0; mt < 4; mt++)
#pragma unroll
                for (int nt = 0; nt < 4; nt++)
                    mma_tf32(acc[mt][nt], af[mt], bf[nt]);
        }
        __syncthreads();
    }

#pragma unroll
    for (int mt = 0; mt < 4; mt++) {
        int rbase = row0 + wm * 64 + mt * 16 + g;
#pragma unroll
        for (int nt = 0; nt < 4; nt++) {
            int cbase = col0 + wn * 32 + nt * 8 + 2 * tg;
#pragma unroll
            for (int half = 0; half < 2; half++) {
                int r = rbase + half * 8;
                if (r >= M) continue;
#pragma unroll
                for (int jj = 0; jj < 2; jj++) {
                    int c = cbase + jj;
                    float v = acc[mt][nt][half * 2 + jj];
                    if (bias) v += bias[c];
                    if (prelu) v = (v >= 0.f) ? v : prelu[c] * v;
                    C[(long)r * Ncol + c] = v;
                }
            }
        }
    }
}

__global__ __launch_bounds__(256) void gemm_tf32(
    const float* __restrict__ A, const float* __restrict__ B, float* __restrict__ C,
    int M, int K, int Ncol,
    const float* __restrict__ bias, const float* __restrict__ prelu)
{
    gemm_body(A, B, C, M, K, Ncol, blockIdx.y * 128, blockIdx.x * 128, bias, prelu);
}

// QKV fused: blockIdx.x selects which projection (0=q,1=k,2=v)
__global__ __launch_bounds__(256) void gemm_qkv(
    const float* __restrict__ A,
    const float* __restrict__ Wq, const float* __restrict__ Wk, const float* __restrict__ Wv,
    float* __restrict__ Q, float* __restrict__ Kb, float* __restrict__ V, int M)
{
    const float* B = (blockIdx.x == 0) ? Wq : (blockIdx.x == 1) ? Wk : Wv;
    float* C = (blockIdx.x == 0) ? Q : (blockIdx.x == 1) ? Kb : V;
    gemm_body(A, B, C, M, 128, 128, blockIdx.y * 128, 0, nullptr, nullptr);
}

// ---------------- attention + aggregate + residual + LN1 ----------------
#define SMAX 256

__global__ __launch_bounds__(128) void k_attn(
    const float* __restrict__ feat,
    const float* __restrict__ ln1g, const float* __restrict__ ln1b)
{
    int node = blockIdx.x;
    int tid = threadIdx.x, lane = tid & 31, warp = tid >> 5;

    __shared__ __align__(16) float q_sh[128];
    __shared__ float m_sh[8], inv_sh[8];
    __shared__ int s_src[SMAX];
    __shared__ float s_w[SMAX * 8];
    __shared__ float red4[4];
    __shared__ float wred[8][8];  // [warp-halfgroup slots][head] scratch

    int rs = g_rowptr[node], re = g_rowptr[node + 1];
    int deg = re - rs;
    q_sh[tid] = g_q[node * 128 + tid];
    __syncthreads();

    int h4 = lane >> 2;
    float4 q4 = *reinterpret_cast<const float4*>(&q_sh[lane * 4]);
    float acc = 0.f;
    int h = tid >> 4;

    if (deg <= SMAX) {
        // ---- fast path: everything in smem ----
        for (int jj = tid; jj < deg; jj += 128) s_src[jj] = g_esrc[rs + jj];
        __syncthreads();

        // scores -> s_w (warp per edge)
        for (int j = warp; j < deg; j += 4) {
            int s = s_src[j];
            float4 k4 = *reinterpret_cast<const float4*>(&g_k[(long)s * 128 + lane * 4]);
            float p = k4.x * q4.x + k4.y * q4.y + k4.z * q4.z + k4.w * q4.w;
            p += __shfl_xor_sync(0xffffffffu, p, 1);
            p += __shfl_xor_sync(0xffffffffu, p, 2);
            if ((lane & 3) == 0) s_w[j * 8 + h4] = p * 0.08838834764831845f;
        }
        __syncthreads();

        // per-head max: 16 threads per head (h = tid>>4, sub = tid&15)
        {
            int sub = tid & 15;
            float lmax = -INFINITY;
            for (int j = sub; j < deg; j += 16) lmax = fmaxf(lmax, s_w[j * 8 + h]);
            lmax = fmaxf(lmax, __shfl_xor_sync(0xffffffffu, lmax, 8));
            lmax = fmaxf(lmax, __shfl_xor_sync(0xffffffffu, lmax, 4));
            lmax = fmaxf(lmax, __shfl_xor_sync(0xffffffffu, lmax, 2));
            lmax = fmaxf(lmax, __shfl_xor_sync(0xffffffffu, lmax, 1));
            if (sub == 0) m_sh[h] = lmax;
        }
        __syncthreads();

        // exp + per-head sum
        {
            int sub = tid & 15;
            float mh = m_sh[h];
            float lsum = 0.f;
            for (int j = sub; j < deg; j += 16) {
                float ex = __expf(s_w[j * 8 + h] - mh);
                s_w[j * 8 + h] = ex;
                lsum += ex;
            }
            lsum += __shfl_xor_sync(0xffffffffu, lsum, 8);
            lsum += __shfl_xor_sync(0xffffffffu, lsum, 4);
            lsum += __shfl_xor_sync(0xffffffffu, lsum, 2);
            lsum += __shfl_xor_sync(0xffffffffu, lsum, 1);
            if (sub == 0) inv_sh[h] = (lsum > 0.f) ? (1.f / lsum) : 0.f;
        }
        __syncthreads();

        // weighted aggregation (unnormalized weights, normalize at end)
        int jj = 0;
        for (; jj + 4 <= deg; jj += 4) {
            float v0 = g_v[(long)s_src[jj + 0] * 128 + tid];
            float v1 = g_v[(long)s_src[jj + 1] * 128 + tid];
            float v2 = g_v[(long)s_src[jj + 2] * 128 + tid];
            float v3 = g_v[(long)s_src[jj + 3] * 128 + tid];
            acc += v0 * s_w[(jj + 0) * 8 + h];
            acc += v1 * s_w[(jj + 1) * 8 + h];
            acc += v2 * s_w[(jj + 2) * 8 + h];
            acc += v3 * s_w[(jj + 3) * 8 + h];
        }
        for (; jj < deg; jj++)
            acc += g_v[(long)s_src[jj] * 128 + tid] * s_w[jj * 8 + h];
        acc *= inv_sh[h];
    } else {
        // ---- slow path: chunked via global scores (rare) ----
        float lmax = -INFINITY;
        for (int j = rs + warp; j < re; j += 4) {
            int s = g_esrc[j];
            float4 k4 = *reinterpret_cast<const float4*>(&g_k[(long)s * 128 + lane * 4]);
            float p = k4.x * q4.x + k4.y * q4.y + k4.z * q4.z + k4.w * q4.w;
            p += __shfl_xor_sync(0xffffffffu, p, 1);
            p += __shfl_xor_sync(0xffffffffu, p, 2);
            float sv = p * 0.08838834764831845f;
            if ((lane & 3) == 0) g_scores[(long)j * 8 + h4] = sv;
            lmax = fmaxf(lmax, sv);
        }
        if ((lane & 3) == 0) wred[warp][h4] = lmax;
        __syncthreads();
        if (tid < 8)
            m_sh[tid] = fmaxf(fmaxf(wred[0][tid], wred[1][tid]),
                              fmaxf(wred[2][tid], wred[3][tid]));
        __syncthreads();

        float lsum = 0.f;
        float mh = (lane < 8) ? m_sh[lane] : 0.f;
        for (int j = rs + warp; j < re; j += 4) {
            if (lane < 8) {
                float ex = __expf(g_scores[(long)j * 8 + lane] - mh);
                g_scores[(long)j * 8 + lane] = ex;
                lsum += ex;
            }
        }
        if (lane < 8) wred[warp][lane] = lsum;
        __syncthreads();
        if (tid < 8) {
            float t = wred[0][tid] + wred[1][tid] + wred[2][tid] + wred[3][tid];
            inv_sh[tid] = (t > 0.f) ? (1.f / t) : 0.f;
        }
        __syncthreads();

        for (int base = rs; base < re; base += SMAX) {
            int cnt = min(SMAX, re - base);
            for (int jj = tid; jj < cnt; jj += 128) s_src[jj] = g_esrc[base + jj];
            __syncthreads();
            for (int idx = tid; idx < cnt * 8; idx += 128)
                s_w[idx] = g_scores[(long)(base + (idx >> 3)) * 8 + (idx & 7)];
            __syncthreads();
            for (int jj = 0; jj < cnt; jj++)
                acc += g_v[(long)s_src[jj] * 128 + tid] * s_w[jj * 8 + h];
            __syncthreads();
        }
        acc *= inv_sh[h];
    }

    // ---- residual + LayerNorm1 ----
    float x = acc + feat[(long)node * 128 + tid];
    float ssum = x;
#pragma unroll
    for (int o = 16; o >= 1; o >>= 1) ssum += __shfl_xor_sync(0xffffffffu, ssum, o);
    if (lane == 0) red4[warp] = ssum;
    __syncthreads();
    float mu = (red4[0] + red4[1] + red4[2] + red4[3]) * (1.f / 128.f);
    __syncthreads();
    float d = x - mu;
    float vv = d * d;
#pragma unroll
    for (int o = 16; o >= 1; o >>= 1) vv += __shfl_xor_sync(0xffffffffu, vv, o);
    if (lane == 0) red4[warp] = vv;
    __syncthreads();
    float var = (red4[0] + red4[1] + red4[2] + red4[3]) * (1.f / 128.f);
    g_rst[(long)node * 128 + tid] = d * rsqrtf(var + 1e-5f) * ln1g[tid] + ln1b[tid];
}

// ---------------- residual + LayerNorm2 -> output ----------------
__global__ __launch_bounds__(128) void k_ln2(
    const float* __restrict__ ln2g, const float* __restrict__ ln2b,
    float* __restrict__ out)
{
    int node = blockIdx.x;
    int tid = threadIdx.x, lane = tid & 31, warp = tid >> 5;
    __shared__ float red4[4];

    float x = g_rst[(long)node * 128 + tid] + g_ffn[(long)node * 128 + tid];
    float ssum = x;
#pragma unroll
    for (int o = 16; o >= 1; o >>= 1) ssum += __shfl_xor_sync(0xffffffffu, ssum, o);
    if (lane == 0) red4[warp] = ssum;
    __syncthreads();
    float mu = (red4[0] + red4[1] + red4[2] + red4[3]) * (1.f / 128.f);
    __syncthreads();
    float d = x - mu;
    float vv = d * d;
#pragma unroll
    for (int o = 16; o >= 1; o >>= 1) vv += __shfl_xor_sync(0xffffffffu, vv, o);
    if (lane == 0) red4[warp] = vv;
    __syncthreads();
    float var = (red4[0] + red4[1] + red4[2] + red4[3]) * (1.f / 128.f);
    out[(long)node * 128 + tid] = d * rsqrtf(var + 1e-5f) * ln2g[tid] + ln2b[tid];
}

// ---------------- launch ----------------
extern "C" void kernel_launch(void* const* d_in, const int* in_sizes, int n_in,
                              void* d_out, int out_size)
{
    const float* feat  = (const float*)d_in[0];
    const int*   src   = (const int*)d_in[1];
    const int*   dst   = (const int*)d_in[2];
    const float* Wq    = (const float*)d_in[3];
    const float* Wk    = (const float*)d_in[4];
    const float* Wv    = (const float*)d_in[5];
    const float* ln1g  = (const float*)d_in[6];
    const float* ln1b  = (const float*)d_in[7];
    const float* ln2g  = (const float*)d_in[8];
    const float* ln2b  = (const float*)d_in[9];
    const float* W1    = (const float*)d_in[10];
    const float* b1    = (const float*)d_in[11];
    const float* prelu = (const float*)d_in[12];
    const float* W2    = (const float*)d_in[13];
    const float* b2    = (const float*)d_in[14];
    float* out = (float*)d_out;

    int N = in_sizes[0] / 128;
    int E = in_sizes[1];

    float *qp, *kp, *vp, *rstp, *ffnp, *hp;
    cudaGetSymbolAddress((void**)&qp, g_q);
    cudaGetSymbolAddress((void**)&kp, g_k);
    cudaGetSymbolAddress((void**)&vp, g_v);
    cudaGetSymbolAddress((void**)&rstp, g_rst);
    cudaGetSymbolAddress((void**)&ffnp, g_ffn);
    cudaGetSymbolAddress((void**)&hp, g_hbuf);

    // CSR build
    k_zero<<<(N + 255) / 256, 256>>>(N);
    k_hist<<<(E + 255) / 256, 256>>>(dst, E);
    k_scan<<<1, 1024>>>(N);
    k_fill<<<(E + 255) / 256, 256>>>(dst, src, E);

    int mblk = (N + 127) / 128;

    // QKV fused (tf32 tensor cores)
    dim3 gqkv(3, mblk);
    gemm_qkv<<<gqkv, 256>>>(feat, Wq, Wk, Wv, qp, kp, vp, N);

    // attention + aggregate + residual + LN1
    k_attn<<<N, 128>>>(feat, ln1g, ln1b);

    // FFN (tf32 tensor cores)
    dim3 gff1(4, mblk);
    gemm_tf32<<<gff1, 256>>>(rstp, W1, hp, N, 128, 512, b1, prelu);
    dim3 gff2(1, mblk);
    gemm_tf32<<<gff2, 256>>>(hp, W2, ffnp, N, 512, 128, b2, nullptr);

    // residual + LN2 -> out
    k_ln2<<<N, 128>>>(ln2g, ln2b, out);
}

// round 7
// speedup vs baseline: 2.3088x; 1.5831x over previous
#include <cuda_runtime.h>
#include <cuda_bf16.h>
#include <stdint.h>
#include <math.h>

#define MAXN 40000
#define MAXE 640000

// ---------------- static device scratch ----------------
__device__ float g_q[MAXN * 128];
__device__ __nv_bfloat16 g_kbf[MAXN * 128];
__device__ float g_v[MAXN * 128];
__device__ float g_rst[MAXN * 128];
__device__ __nv_bfloat16 g_rstbf[MAXN * 128];
__device__ float g_ffn[MAXN * 128];
__device__ __nv_bfloat16 g_hbf[MAXN * 512];
__device__ __nv_bfloat16 g_featbf[MAXN * 128];
__device__ __nv_bfloat16 g_WqT[128 * 128];
__device__ __nv_bfloat16 g_WkT[128 * 128];
__device__ __nv_bfloat16 g_WvT[128 * 128];
__device__ __nv_bfloat16 g_W1T[512 * 128];   // [n][k]
__device__ __nv_bfloat16 g_W2T[128 * 512];   // [n][k]
__device__ float g_scores[MAXE * 8];
__device__ int g_deg[MAXN];
__device__ int g_cursor[MAXN];
__device__ int g_rowptr[MAXN + 1];
__device__ int g_esrc[MAXE];
__device__ int g_part[512];

// ---------------- converts ----------------
__global__ void k_cvt_feat(const float* __restrict__ f, int n) {
    int i = (blockIdx.x * blockDim.x + threadIdx.x) * 4;
    if (i < n) {
        float4 v = *reinterpret_cast<const float4*>(f + i);
        __nv_bfloat162 a, b;
        a.x = __float2bfloat16_rn(v.x); a.y = __float2bfloat16_rn(v.y);
        b.x = __float2bfloat16_rn(v.z); b.y = __float2bfloat16_rn(v.w);
        *reinterpret_cast<__nv_bfloat162*>(&g_featbf[i]) = a;
        *reinterpret_cast<__nv_bfloat162*>(&g_featbf[i + 2]) = b;
    }
}

// transpose+convert weights: in [Kd][Nd] f32 -> out [Nd][Kd] bf16
__global__ void k_cvt_w(const float* __restrict__ Wq, const float* __restrict__ Wk,
                        const float* __restrict__ Wv, const float* __restrict__ W1,
                        const float* __restrict__ W2) {
    int m = blockIdx.y;
    const float* src; __nv_bfloat16* dst; int Kd, Nd;
    if (m == 0) { src = Wq; dst = g_WqT; Kd = 128; Nd = 128; }
    else if (m == 1) { src = Wk; dst = g_WkT; Kd = 128; Nd = 128; }
    else if (m == 2) { src = Wv; dst = g_WvT; Kd = 128; Nd = 128; }
    else if (m == 3) { src = W1; dst = g_W1T; Kd = 128; Nd = 512; }
    else { src = W2; dst = g_W2T; Kd = 512; Nd = 128; }
    int tot = Kd * Nd;
    for (int i = blockIdx.x * blockDim.x + threadIdx.x; i < tot;
         i += gridDim.x * blockDim.x) {
        int nn = i / Kd, kk = i - nn * Kd;
        dst[i] = __float2bfloat16_rn(src[kk * Nd + nn]);
    }
}

// ---------------- CSR build ----------------
__global__ void k_hist(const int* __restrict__ dst, int E) {
    int e = blockIdx.x * blockDim.x + threadIdx.x;
    if (e < E) atomicAdd(&g_deg[dst[e]], 1);
}

__global__ void k_scan1(int n) {
    __shared__ int sh[256];
    int b = blockIdx.x, t = threadIdx.x;
    int i = b * 256 + t;
    int v = (i < n) ? g_deg[i] : 0;
    sh[t] = v; __syncthreads();
    for (int off = 1; off < 256; off <<= 1) {
        int x = (t >= off) ? sh[t - off] : 0; __syncthreads();
        sh[t] += x; __syncthreads();
    }
    if (i < n) g_rowptr[i + 1] = sh[t];
    if (t == 255) g_part[b] = sh[255];
    if (b == 0 && t == 0) g_rowptr[0] = 0;
}

__global__ void k_scan2(int nb) {
    __shared__ int sh[256];
    int t = threadIdx.x;
    int v = (t < nb) ? g_part[t] : 0;
    sh[t] = v; __syncthreads();
    for (int off = 1; off < 256; off <<= 1) {
        int x = (t >= off) ? sh[t - off] : 0; __syncthreads();
        sh[t] += x; __syncthreads();
    }
    if (t < nb) g_part[t] = sh[t] - v;  // exclusive
}

__global__ void k_scan3(int n) {
    int i = blockIdx.x * blockDim.x + threadIdx.x;
    if (i < n) g_rowptr[i + 1] += g_part[i >> 8];
}

__global__ void k_fill(const int* __restrict__ dst, const int* __restrict__ src, int E) {
    int e = blockIdx.x * blockDim.x + threadIdx.x;
    if (e < E) {
        int d = dst[e];
        int pos = atomicAdd(&g_cursor[d], 1);
        g_esrc[g_rowptr[d] + pos] = src[e];
    }
}

// ---------------- bf16 tensor-core GEMM ----------------
#define ASTRIDE 20  // u32 per smem row: 16 used + 4 pad (conflict-free fragment LDS)

__device__ __forceinline__ void mma_bf16(float* c, const unsigned* a, const unsigned* b) {
    asm volatile(
        "mma.sync.aligned.m16n8k16.row.col.f32.bf16.bf16.f32 "
        "{%0,%1,%2,%3}, {%4,%5,%6,%7}, {%8,%9}, {%0,%1,%2,%3};\n"
        : "+f"(c[0]), "+f"(c[1]), "+f"(c[2]), "+f"(c[3])
        : "r"(a[0]), "r"(a[1]), "r"(a[2]), "r"(a[3]), "r"(b[0]), "r"(b[1]));
}

__device__ __forceinline__ void cp16(unsigned int dsh, const void* src, int nbytes) {
    asm volatile("cp.async.cg.shared.global [%0], [%1], 16, %2;\n"
                 :: "r"(dsh), "l"(src), "r"(nbytes));
}

// BM=128 BN=128 BK=32, 256 threads, cp.async double-buffered.
// A: bf16 [M][Kd] row-major.  BT: bf16 [Ncol][Kd] row-major (pre-transposed).
__device__ __forceinline__ void gemm_core(
    const __nv_bfloat16* __restrict__ A, const __nv_bfloat16* __restrict__ BT,
    int M, int Kd, int Ncol, int row0, int col0,
    float* __restrict__ Cf, __nv_bfloat16* __restrict__ Cb,
    const float* __restrict__ bias, const float* __restrict__ prelu)
{
    __shared__ unsigned As[2][128 * ASTRIDE];
    __shared__ unsigned Bs[2][128 * ASTRIDE];

    int tid = threadIdx.x, lane = tid & 31, warp = tid >> 5;
    int wm = warp & 1, wn = warp >> 1;
    int g = lane >> 2, tg = lane & 3;

    float acc[4][4][4];
#pragma unroll
    for (int mt = 0; mt < 4; mt++)
#pragma unroll
        for (int nt = 0; nt < 4; nt++)
#pragma unroll
            for (int r = 0; r < 4; r++) acc[mt][nt][r] = 0.f;

    int lrow = tid >> 2;           // 0..63 (x2)
    int lq = tid & 3;              // 16B chunk within 64B row-tile
    unsigned int saA0 = (unsigned int)__cvta_generic_to_shared(&As[0][0]);
    unsigned int saB0 = (unsigned int)__cvta_generic_to_shared(&Bs[0][0]);

    int KT = Kd >> 5;

    auto issue = [&](int s, int k0) {
        unsigned int baseA = saA0 + (unsigned int)s * 128 * ASTRIDE * 4;
        unsigned int baseB = saB0 + (unsigned int)s * 128 * ASTRIDE * 4;
#pragma unroll
        for (int r = 0; r < 2; r++) {
            int row = lrow + r * 64;
            unsigned int doff = (unsigned int)(row * ASTRIDE + lq * 4) * 4;
            const __nv_bfloat16* sA = A + (long)(row0 + row) * Kd + k0 + lq * 8;
            cp16(baseA + doff, sA, (row0 + row < M) ? 16 : 0);
            const __nv_bfloat16* sB = BT + (long)(col0 + row) * Kd + k0 + lq * 8;
            cp16(baseB + doff, sB, 16);
        }
        asm volatile("cp.async.commit_group;\n");
    };

    issue(0, 0);
    for (int kt = 0; kt < KT; kt++) {
        int cur = kt & 1;
        if (kt + 1 < KT) {
            issue(cur ^ 1, (kt + 1) * 32);
            asm volatile("cp.async.wait_group 1;\n");
        } else {
            asm volatile("cp.async.wait_group 0;\n");
        }
        __syncthreads();

        const unsigned* Ac = As[cur];
        const unsigned* Bc = Bs[cur];
#pragma unroll
        for (int kb = 0; kb < 2; kb++) {
            int kk2 = kb * 8;
            unsigned af[4][4];
#pragma unroll
            for (int mt = 0; mt < 4; mt++) {
                int mr = (wm * 64 + mt * 16 + g) * ASTRIDE;
                af[mt][0] = Ac[mr + kk2 + tg];
                af[mt][1] = Ac[mr + 8 * ASTRIDE + kk2 + tg];
                af[mt][2] = Ac[mr + kk2 + tg + 4];
                af[mt][3] = Ac[mr + 8 * ASTRIDE + kk2 + tg + 4];
            }
            unsigned bf[4][2];
#pragma unroll
            for (int nt = 0; nt < 4; nt++) {
                int nr = (wn * 32 + nt * 8 + g) * ASTRIDE;
                bf[nt][0] = Bc[nr + kk2 + tg];
                bf[nt][1] = Bc[nr + kk2 + tg + 4];
            }
#pragma unroll
            for (int mt = 0; mt < 4; mt++)
#pragma unroll
                for (int nt = 0; nt < 4; nt++)
                    mma_bf16(acc[mt][nt], af[mt], bf[nt]);
        }
        __syncthreads();
    }

    // epilogue
#pragma unroll
    for (int mt = 0; mt < 4; mt++) {
        int rbase = row0 + wm * 64 + mt * 16 + g;
#pragma unroll
        for (int nt = 0; nt < 4; nt++) {
            int c = col0 + wn * 32 + nt * 8 + 2 * tg;
#pragma unroll
            for (int half = 0; half < 2; half++) {
                int r = rbase + half * 8;
                if (r >= M) continue;
                float v0 = acc[mt][nt][half * 2 + 0];
                float v1 = acc[mt][nt][half * 2 + 1];
                if (bias) { v0 += bias[c]; v1 += bias[c + 1]; }
                if (prelu) {
                    v0 = (v0 >= 0.f) ? v0 : prelu[c] * v0;
                    v1 = (v1 >= 0.f) ? v1 : prelu[c + 1] * v1;
                }
                if (Cf) {
                    float2 o = make_float2(v0, v1);
                    *reinterpret_cast<float2*>(&Cf[(long)r * Ncol + c]) = o;
                } else {
                    __nv_bfloat162 o;
                    o.x = __float2bfloat16_rn(v0);
                    o.y = __float2bfloat16_rn(v1);
                    *reinterpret_cast<__nv_bfloat162*>(&Cb[(long)r * Ncol + c]) = o;
                }
            }
        }
    }
}

__global__ __launch_bounds__(256) void gemm_qkv(int M) {
    int which = blockIdx.x;
    const __nv_bfloat16* BT = (which == 0) ? g_WqT : (which == 1) ? g_WkT : g_WvT;
    float* Cf = (which == 0) ? g_q : (which == 2) ? g_v : nullptr;
    __nv_bfloat16* Cb = (which == 1) ? g_kbf : nullptr;
    gemm_core(g_featbf, BT, M, 128, 128, blockIdx.y * 128, 0, Cf, Cb, nullptr, nullptr);
}

__global__ __launch_bounds__(256) void gemm_ffn1(int M, const float* __restrict__ b1,
                                                 const float* __restrict__ prelu) {
    gemm_core(g_rstbf, g_W1T, M, 128, 512, blockIdx.y * 128, blockIdx.x * 128,
              nullptr, g_hbf, b1, prelu);
}

__global__ __launch_bounds__(256) void gemm_ffn2(int M, const float* __restrict__ b2) {
    gemm_core(g_hbf, g_W2T, M, 512, 128, blockIdx.y * 128, 0, g_ffn, nullptr, b2, nullptr);
}

// ---------------- attention + aggregate + residual + LN1 ----------------
#define SMAX 256

__device__ __forceinline__ float kdot_bf16(const __nv_bfloat16* kr, float4 q4) {
    uint2 u = *reinterpret_cast<const uint2*>(kr);
    __nv_bfloat162 b0 = *reinterpret_cast<__nv_bfloat162*>(&u.x);
    __nv_bfloat162 b1 = *reinterpret_cast<__nv_bfloat162*>(&u.y);
    float2 f0 = __bfloat1622float2(b0), f1 = __bfloat1622float2(b1);
    return f0.x * q4.x + f0.y * q4.y + f1.x * q4.z + f1.y * q4.w;
}

__global__ __launch_bounds__(128) void k_attn(
    const float* __restrict__ feat,
    const float* __restrict__ ln1g, const float* __restrict__ ln1b)
{
    int node = blockIdx.x;
    int tid = threadIdx.x, lane = tid & 31, warp = tid >> 5;

    __shared__ __align__(16) float q_sh[128];
    __shared__ float m_sh[8], inv_sh[8];
    __shared__ int s_src[SMAX];
    __shared__ float s_w[SMAX * 8];
    __shared__ float red4[4];
    __shared__ float wred[8][8];

    int rs = g_rowptr[node], re = g_rowptr[node + 1];
    int deg = re - rs;
    q_sh[tid] = g_q[node * 128 + tid];
    __syncthreads();

    int h4 = lane >> 2;
    float4 q4 = *reinterpret_cast<const float4*>(&q_sh[lane * 4]);
    float acc = 0.f;
    int h = tid >> 4;

    if (deg <= SMAX) {
        for (int jj = tid; jj < deg; jj += 128) s_src[jj] = g_esrc[rs + jj];
        __syncthreads();

        for (int j = warp; j < deg; j += 4) {
            int s = s_src[j];
            float p = kdot_bf16(&g_kbf[(long)s * 128 + lane * 4], q4);
            p += __shfl_xor_sync(0xffffffffu, p, 1);
            p += __shfl_xor_sync(0xffffffffu, p, 2);
            if ((lane & 3) == 0) s_w[j * 8 + h4] = p * 0.08838834764831845f;
        }
        __syncthreads();

        {
            int sub = tid & 15;
            float lmax = -INFINITY;
            for (int j = sub; j < deg; j += 16) lmax = fmaxf(lmax, s_w[j * 8 + h]);
            lmax = fmaxf(lmax, __shfl_xor_sync(0xffffffffu, lmax, 8));
            lmax = fmaxf(lmax, __shfl_xor_sync(0xffffffffu, lmax, 4));
            lmax = fmaxf(lmax, __shfl_xor_sync(0xffffffffu, lmax, 2));
            lmax = fmaxf(lmax, __shfl_xor_sync(0xffffffffu, lmax, 1));
            if (sub == 0) m_sh[h] = lmax;
        }
        __syncthreads();
        {
            int sub = tid & 15;
            float mh = m_sh[h];
            float lsum = 0.f;
            for (int j = sub; j < deg; j += 16) {
                float ex = __expf(s_w[j * 8 + h] - mh);
                s_w[j * 8 + h] = ex;
                lsum += ex;
            }
            lsum += __shfl_xor_sync(0xffffffffu, lsum, 8);
            lsum += __shfl_xor_sync(0xffffffffu, lsum, 4);
            lsum += __shfl_xor_sync(0xffffffffu, lsum, 2);
            lsum += __shfl_xor_sync(0xffffffffu, lsum, 1);
            if (sub == 0) inv_sh[h] = (lsum > 0.f) ? (1.f / lsum) : 0.f;
        }
        __syncthreads();

        int jj = 0;
        for (; jj + 4 <= deg; jj += 4) {
            float v0 = g_v[(long)s_src[jj + 0] * 128 + tid];
            float v1 = g_v[(long)s_src[jj + 1] * 128 + tid];
            float v2 = g_v[(long)s_src[jj + 2] * 128 + tid];
            float v3 = g_v[(long)s_src[jj + 3] * 128 + tid];
            acc += v0 * s_w[(jj + 0) * 8 + h];
            acc += v1 * s_w[(jj + 1) * 8 + h];
            acc += v2 * s_w[(jj + 2) * 8 + h];
            acc += v3 * s_w[(jj + 3) * 8 + h];
        }
        for (; jj < deg; jj++)
            acc += g_v[(long)s_src[jj] * 128 + tid] * s_w[jj * 8 + h];
        acc *= inv_sh[h];
    } else {
        float lmax = -INFINITY;
        for (int j = rs + warp; j < re; j += 4) {
            int s = g_esrc[j];
            float p = kdot_bf16(&g_kbf[(long)s * 128 + lane * 4], q4);
            p += __shfl_xor_sync(0xffffffffu, p, 1);
            p += __shfl_xor_sync(0xffffffffu, p, 2);
            float sv = p * 0.08838834764831845f;
            if ((lane & 3) == 0) g_scores[(long)j * 8 + h4] = sv;
            lmax = fmaxf(lmax, sv);
        }
        if ((lane & 3) == 0) wred[warp][h4] = lmax;
        __syncthreads();
        if (tid < 8)
            m_sh[tid] = fmaxf(fmaxf(wred[0][tid], wred[1][tid]),
                              fmaxf(wred[2][tid], wred[3][tid]));
        __syncthreads();

        float lsum = 0.f;
        float mh = (lane < 8) ? m_sh[lane] : 0.f;
        for (int j = rs + warp; j < re; j += 4) {
            if (lane < 8) {
                float ex = __expf(g_scores[(long)j * 8 + lane] - mh);
                g_scores[(long)j * 8 + lane] = ex;
                lsum += ex;
            }
        }
        if (lane < 8) wred[warp][lane] = lsum;
        __syncthreads();
        if (tid < 8) {
            float t = wred[0][tid] + wred[1][tid] + wred[2][tid] + wred[3][tid];
            inv_sh[tid] = (t > 0.f) ? (1.f / t) : 0.f;
        }
        __syncthreads();

        for (int base = rs; base < re; base += SMAX) {
            int cnt = min(SMAX, re - base);
            for (int jj = tid; jj < cnt; jj += 128) s_src[jj] = g_esrc[base + jj];
            __syncthreads();
            for (int idx = tid; idx < cnt * 8; idx += 128)
                s_w[idx] = g_scores[(long)(base + (idx >> 3)) * 8 + (idx & 7)];
            __syncthreads();
            for (int jj = 0; jj < cnt; jj++)
                acc += g_v[(long)s_src[jj] * 128 + tid] * s_w[jj * 8 + h];
            __syncthreads();
        }
        acc *= inv_sh[h];
    }

    // residual + LN1 (+ bf16 copy for FFN1)
    float x = acc + feat[(long)node * 128 + tid];
    float ssum = x;
#pragma unroll
    for (int o = 16; o >= 1; o >>= 1) ssum += __shfl_xor_sync(0xffffffffu, ssum, o);
    if (lane == 0) red4[warp] = ssum;
    __syncthreads();
    float mu = (red4[0] + red4[1] + red4[2] + red4[3]) * (1.f / 128.f);
    __syncthreads();
    float d = x - mu;
    float vv = d * d;
#pragma unroll
    for (int o = 16; o >= 1; o >>= 1) vv += __shfl_xor_sync(0xffffffffu, vv, o);
    if (lane == 0) red4[warp] = vv;
    __syncthreads();
    float var = (red4[0] + red4[1] + red4[2] + red4[3]) * (1.f / 128.f);
    float y = d * rsqrtf(var + 1e-5f) * ln1g[tid] + ln1b[tid];
    g_rst[(long)node * 128 + tid] = y;
    g_rstbf[(long)node * 128 + tid] = __float2bfloat16_rn(y);
}

// ---------------- residual + LayerNorm2 -> output ----------------
__global__ __launch_bounds__(128) void k_ln2(
    const float* __restrict__ ln2g, const float* __restrict__ ln2b,
    float* __restrict__ out)
{
    int node = blockIdx.x;
    int tid = threadIdx.x, lane = tid & 31, warp = tid >> 5;
    __shared__ float red4[4];

    float x = g_rst[(long)node * 128 + tid] + g_ffn[(long)node * 128 + tid];
    float ssum = x;
#pragma unroll
    for (int o = 16; o >= 1; o >>= 1) ssum += __shfl_xor_sync(0xffffffffu, ssum, o);
    if (lane == 0) red4[warp] = ssum;
    __syncthreads();
    float mu = (red4[0] + red4[1] + red4[2] + red4[3]) * (1.f / 128.f);
    __syncthreads();
    float d = x - mu;
    float vv = d * d;
#pragma unroll
    for (int o = 16; o >= 1; o >>= 1) vv += __shfl_xor_sync(0xffffffffu, vv, o);
    if (lane == 0) red4[warp] = vv;
    __syncthreads();
    float var = (red4[0] + red4[1] + red4[2] + red4[3]) * (1.f / 128.f);
    out[(long)node * 128 + tid] = d * rsqrtf(var + 1e-5f) * ln2g[tid] + ln2b[tid];
}

// ---------------- launch ----------------
extern "C" void kernel_launch(void* const* d_in, const int* in_sizes, int n_in,
                              void* d_out, int out_size)
{
    const float* feat  = (const float*)d_in[0];
    const int*   src   = (const int*)d_in[1];
    const int*   dst   = (const int*)d_in[2];
    const float* Wq    = (const float*)d_in[3];
    const float* Wk    = (const float*)d_in[4];
    const float* Wv    = (const float*)d_in[5];
    const float* ln1g  = (const float*)d_in[6];
    const float* ln1b  = (const float*)d_in[7];
    const float* ln2g  = (const float*)d_in[8];
    const float* ln2b  = (const float*)d_in[9];
    const float* W1    = (const float*)d_in[10];
    const float* b1    = (const float*)d_in[11];
    const float* prelu = (const float*)d_in[12];
    const float* W2    = (const float*)d_in[13];
    const float* b2    = (const float*)d_in[14];
    float* out = (float*)d_out;

    int N = in_sizes[0] / 128;
    int E = in_sizes[1];

    void *degp, *curp;
    cudaGetSymbolAddress(&degp, g_deg);
    cudaGetSymbolAddress(&curp, g_cursor);
    cudaMemsetAsync(degp, 0, (size_t)N * 4);
    cudaMemsetAsync(curp, 0, (size_t)N * 4);

    // converts
    k_cvt_feat<<<(N * 128 / 4 + 255) / 256, 256>>>(feat, N * 128);
    dim3 gw(64, 5);
    k_cvt_w<<<gw, 256>>>(Wq, Wk, Wv, W1, W2);

    // CSR build
    k_hist<<<(E + 255) / 256, 256>>>(dst, E);
    int nb = (N + 255) / 256;
    k_scan1<<<nb, 256>>>(N);
    k_scan2<<<1, 256>>>(nb);
    k_scan3<<<nb, 256>>>(N);
    k_fill<<<(E + 255) / 256, 256>>>(dst, src, E);

    int mblk = (N + 127) / 128;

    // QKV (bf16 tensor cores)
    dim3 gqkv(3, mblk);
    gemm_qkv<<<gqkv, 256>>>(N);

    // attention + aggregate + residual + LN1
    k_attn<<<N, 128>>>(feat, ln1g, ln1b);

    // FFN
    dim3 gff1(4, mblk);
    gemm_ffn1<<<gff1, 256>>>(N, b1, prelu);
    dim3 gff2(1, mblk);
    gemm_ffn2<<<gff2, 256>>>(N, b2);

    // residual + LN2 -> out
    k_ln2<<<N, 128>>>(ln2g, ln2b, out);
}

// round 8
// speedup vs baseline: 3.2126x; 1.3915x over previous
#include <cuda_runtime.h>
#include <cuda_bf16.h>
#include <stdint.h>
#include <math.h>

#define MAXN 40000
#define MAXE 640000

// ---------------- static device scratch ----------------
__device__ float g_q[MAXN * 128];
__device__ __nv_bfloat16 g_kbf[MAXN * 128];
__device__ float g_v[MAXN * 128];
__device__ float g_rst[MAXN * 128];
__device__ __nv_bfloat16 g_rstbf[MAXN * 128];
__device__ float g_ffn[MAXN * 128];
__device__ __nv_bfloat16 g_hbf[MAXN * 512];
__device__ __nv_bfloat16 g_featbf[MAXN * 128];
__device__ __nv_bfloat16 g_WqT[128 * 128];
__device__ __nv_bfloat16 g_WkT[128 * 128];
__device__ __nv_bfloat16 g_WvT[128 * 128];
__device__ __nv_bfloat16 g_W1T[512 * 128];   // [n][k]
__device__ __nv_bfloat16 g_W2T[128 * 512];   // [n][k]
__device__ int g_deg[MAXN];
__device__ int g_cursor[MAXN];
__device__ int g_rowptr[MAXN + 1];
__device__ int g_esrc[MAXE];
__device__ int g_part[512];

// ---------------- converts ----------------
__global__ void k_cvt_feat(const float* __restrict__ f, int n) {
    int i = (blockIdx.x * blockDim.x + threadIdx.x) * 4;
    if (i < n) {
        float4 v = *reinterpret_cast<const float4*>(f + i);
        __nv_bfloat162 a, b;
        a.x = __float2bfloat16_rn(v.x); a.y = __float2bfloat16_rn(v.y);
        b.x = __float2bfloat16_rn(v.z); b.y = __float2bfloat16_rn(v.w);
        *reinterpret_cast<__nv_bfloat162*>(&g_featbf[i]) = a;
        *reinterpret_cast<__nv_bfloat162*>(&g_featbf[i + 2]) = b;
    }
}

// transpose+convert weights: in [Kd][Nd] f32 -> out [Nd][Kd] bf16
__global__ void k_cvt_w(const float* __restrict__ Wq, const float* __restrict__ Wk,
                        const float* __restrict__ Wv, const float* __restrict__ W1,
                        const float* __restrict__ W2) {
    int m = blockIdx.y;
    const float* src; __nv_bfloat16* dst; int Kd, Nd;
    if (m == 0) { src = Wq; dst = g_WqT; Kd = 128; Nd = 128; }
    else if (m == 1) { src = Wk; dst = g_WkT; Kd = 128; Nd = 128; }
    else if (m == 2) { src = Wv; dst = g_WvT; Kd = 128; Nd = 128; }
    else if (m == 3) { src = W1; dst = g_W1T; Kd = 128; Nd = 512; }
    else { src = W2; dst = g_W2T; Kd = 512; Nd = 128; }
    int tot = Kd * Nd;
    for (int i = blockIdx.x * blockDim.x + threadIdx.x; i < tot;
         i += gridDim.x * blockDim.x) {
        int nn = i / Kd, kk = i - nn * Kd;
        dst[i] = __float2bfloat16_rn(src[kk * Nd + nn]);
    }
}

// ---------------- CSR build ----------------
__global__ void k_hist(const int* __restrict__ dst, int E) {
    int e = blockIdx.x * blockDim.x + threadIdx.x;
    if (e < E) atomicAdd(&g_deg[dst[e]], 1);
}

__global__ void k_scan1(int n) {
    __shared__ int sh[256];
    int b = blockIdx.x, t = threadIdx.x;
    int i = b * 256 + t;
    int v = (i < n) ? g_deg[i] : 0;
    sh[t] = v; __syncthreads();
    for (int off = 1; off < 256; off <<= 1) {
        int x = (t >= off) ? sh[t - off] : 0; __syncthreads();
        sh[t] += x; __syncthreads();
    }
    if (i < n) g_rowptr[i + 1] = sh[t];
    if (t == 255) g_part[b] = sh[255];
    if (b == 0 && t == 0) g_rowptr[0] = 0;
}

__global__ void k_scan2(int nb) {
    __shared__ int sh[256];
    int t = threadIdx.x;
    int v = (t < nb) ? g_part[t] : 0;
    sh[t] = v; __syncthreads();
    for (int off = 1; off < 256; off <<= 1) {
        int x = (t >= off) ? sh[t - off] : 0; __syncthreads();
        sh[t] += x; __syncthreads();
    }
    if (t < nb) g_part[t] = sh[t] - v;  // exclusive
}

__global__ void k_scan3(int n) {
    int i = blockIdx.x * blockDim.x + threadIdx.x;
    if (i < n) g_rowptr[i + 1] += g_part[i >> 8];
}

__global__ void k_fill(const int* __restrict__ dst, const int* __restrict__ src, int E) {
    int e = blockIdx.x * blockDim.x + threadIdx.x;
    if (e < E) {
        int d = dst[e];
        int pos = atomicAdd(&g_cursor[d], 1);
        g_esrc[g_rowptr[d] + pos] = src[e];
    }
}

// ---------------- bf16 tensor-core GEMM ----------------
#define ASTRIDE 20  // u32 per smem row: 16 used + 4 pad (conflict-free fragment LDS)

__device__ __forceinline__ void mma_bf16(float* c, const unsigned* a, const unsigned* b) {
    asm volatile(
        "mma.sync.aligned.m16n8k16.row.col.f32.bf16.bf16.f32 "
        "{%0,%1,%2,%3}, {%4,%5,%6,%7}, {%8,%9}, {%0,%1,%2,%3};\n"
        : "+f"(c[0]), "+f"(c[1]), "+f"(c[2]), "+f"(c[3])
        : "r"(a[0]), "r"(a[1]), "r"(a[2]), "r"(a[3]), "r"(b[0]), "r"(b[1]));
}

__device__ __forceinline__ void cp16(unsigned int dsh, const void* src, int nbytes) {
    asm volatile("cp.async.cg.shared.global [%0], [%1], 16, %2;\n"
                 :: "r"(dsh), "l"(src), "r"(nbytes));
}

// BM=128 BN=128 BK=32, 256 threads, cp.async double-buffered.
// A: bf16 [M][Kd] row-major.  BT: bf16 [Ncol][Kd] row-major (pre-transposed).
__device__ __forceinline__ void gemm_core(
    const __nv_bfloat16* __restrict__ A, const __nv_bfloat16* __restrict__ BT,
    int M, int Kd, int Ncol, int row0, int col0,
    float* __restrict__ Cf, __nv_bfloat16* __restrict__ Cb,
    const float* __restrict__ bias, const float* __restrict__ prelu)
{
    __shared__ unsigned As[2][128 * ASTRIDE];
    __shared__ unsigned Bs[2][128 * ASTRIDE];

    int tid = threadIdx.x, lane = tid & 31, warp = tid >> 5;
    int wm = warp & 1, wn = warp >> 1;
    int g = lane >> 2, tg = lane & 3;

    float acc[4][4][4];
#pragma unroll
    for (int mt = 0; mt < 4; mt++)
#pragma unroll
        for (int nt = 0; nt < 4; nt++)
#pragma unroll
            for (int r = 0; r < 4; r++) acc[mt][nt][r] = 0.f;

    int lrow = tid >> 2;           // 0..63 (x2)
    int lq = tid & 3;              // 16B chunk within 64B row-tile
    unsigned int saA0 = (unsigned int)__cvta_generic_to_shared(&As[0][0]);
    unsigned int saB0 = (unsigned int)__cvta_generic_to_shared(&Bs[0][0]);

    int KT = Kd >> 5;

    auto issue = [&](int s, int k0) {
        unsigned int baseA = saA0 + (unsigned int)s * 128 * ASTRIDE * 4;
        unsigned int baseB = saB0 + (unsigned int)s * 128 * ASTRIDE * 4;
#pragma unroll
        for (int r = 0; r < 2; r++) {
            int row = lrow + r * 64;
            unsigned int doff = (unsigned int)(row * ASTRIDE + lq * 4) * 4;
            const __nv_bfloat16* sA = A + (long)(row0 + row) * Kd + k0 + lq * 8;
            cp16(baseA + doff, sA, (row0 + row < M) ? 16 : 0);
            const __nv_bfloat16* sB = BT + (long)(col0 + row) * Kd + k0 + lq * 8;
            cp16(baseB + doff, sB, 16);
        }
        asm volatile("cp.async.commit_group;\n");
    };

    issue(0, 0);
    for (int kt = 0; kt < KT; kt++) {
        int cur = kt & 1;
        if (kt + 1 < KT) {
            issue(cur ^ 1, (kt + 1) * 32);
            asm volatile("cp.async.wait_group 1;\n");
        } else {
            asm volatile("cp.async.wait_group 0;\n");
        }
        __syncthreads();

        const unsigned* Ac = As[cur];
        const unsigned* Bc = Bs[cur];
#pragma unroll
        for (int kb = 0; kb < 2; kb++) {
            int kk2 = kb * 8;
            unsigned af[4][4];
#pragma unroll
            for (int mt = 0; mt < 4; mt++) {
                int mr = (wm * 64 + mt * 16 + g) * ASTRIDE;
                af[mt][0] = Ac[mr + kk2 + tg];
                af[mt][1] = Ac[mr + 8 * ASTRIDE + kk2 + tg];
                af[mt][2] = Ac[mr + kk2 + tg + 4];
                af[mt][3] = Ac[mr + 8 * ASTRIDE + kk2 + tg + 4];
            }
            unsigned bf[4][2];
#pragma unroll
            for (int nt = 0; nt < 4; nt++) {
                int nr = (wn * 32 + nt * 8 + g) * ASTRIDE;
                bf[nt][0] = Bc[nr + kk2 + tg];
                bf[nt][1] = Bc[nr + kk2 + tg + 4];
            }
#pragma unroll
            for (int mt = 0; mt < 4; mt++)
#pragma unroll
                for (int nt = 0; nt < 4; nt++)
                    mma_bf16(acc[mt][nt], af[mt], bf[nt]);
        }
        __syncthreads();
    }

    // epilogue
#pragma unroll
    for (int mt = 0; mt < 4; mt++) {
        int rbase = row0 + wm * 64 + mt * 16 + g;
#pragma unroll
        for (int nt = 0; nt < 4; nt++) {
            int c = col0 + wn * 32 + nt * 8 + 2 * tg;
#pragma unroll
            for (int half = 0; half < 2; half++) {
                int r = rbase + half * 8;
                if (r >= M) continue;
                float v0 = acc[mt][nt][half * 2 + 0];
                float v1 = acc[mt][nt][half * 2 + 1];
                if (bias) { v0 += bias[c]; v1 += bias[c + 1]; }
                if (prelu) {
                    v0 = (v0 >= 0.f) ? v0 : prelu[c] * v0;
                    v1 = (v1 >= 0.f) ? v1 : prelu[c + 1] * v1;
                }
                if (Cf) {
                    float2 o = make_float2(v0, v1);
                    *reinterpret_cast<float2*>(&Cf[(long)r * Ncol + c]) = o;
                } else {
                    __nv_bfloat162 o;
                    o.x = __float2bfloat16_rn(v0);
                    o.y = __float2bfloat16_rn(v1);
                    *reinterpret_cast<__nv_bfloat162*>(&Cb[(long)r * Ncol + c]) = o;
                }
            }
        }
    }
}

__global__ __launch_bounds__(256) void gemm_qkv(int M) {
    int which = blockIdx.x;
    const __nv_bfloat16* BT = (which == 0) ? g_WqT : (which == 1) ? g_WkT : g_WvT;
    float* Cf = (which == 0) ? g_q : (which == 2) ? g_v : nullptr;
    __nv_bfloat16* Cb = (which == 1) ? g_kbf : nullptr;
    gemm_core(g_featbf, BT, M, 128, 128, blockIdx.y * 128, 0, Cf, Cb, nullptr, nullptr);
}

__global__ __launch_bounds__(256) void gemm_ffn1(int M, const float* __restrict__ b1,
                                                 const float* __restrict__ prelu) {
    gemm_core(g_rstbf, g_W1T, M, 128, 512, blockIdx.y * 128, blockIdx.x * 128,
              nullptr, g_hbf, b1, prelu);
}

__global__ __launch_bounds__(256) void gemm_ffn2(int M, const float* __restrict__ b2) {
    gemm_core(g_hbf, g_W2T, M, 512, 128, blockIdx.y * 128, 0, g_ffn, nullptr, b2, nullptr);
}

// ---------------- attention: warp per node, online softmax, fully register-resident ----------------
__global__ __launch_bounds__(256) void k_attn(
    const float* __restrict__ feat,
    const float* __restrict__ ln1g, const float* __restrict__ ln1b, int N)
{
    int gw = (blockIdx.x * blockDim.x + threadIdx.x) >> 5;
    if (gw >= N) return;
    int lane = threadIdx.x & 31;
    int node = gw;

    int rs = g_rowptr[node], re = g_rowptr[node + 1];

    // lane l owns channels 4l..4l+3 (head = l>>2)
    float4 q4 = *reinterpret_cast<const float4*>(&g_q[(long)node * 128 + lane * 4]);
    const float scale = 0.08838834764831845f;  // 1/sqrt(128)
    q4.x *= scale; q4.y *= scale; q4.z *= scale; q4.w *= scale;

    float m = -INFINITY, ssum = 0.f;
    float a0 = 0.f, a1 = 0.f, a2 = 0.f, a3 = 0.f;

    for (int base = rs; base < re; base += 32) {
        int nchunk = min(32, re - base);
        int sreg = (base + lane < re) ? g_esrc[base + lane] : 0;
        for (int j = 0; j < nchunk; j++) {
            int s = __shfl_sync(0xffffffffu, sreg, j);
            // scaled head-dot (4-lane butterfly -> all 4 lanes of head group hold it)
            uint2 u = *reinterpret_cast<const uint2*>(&g_kbf[(long)s * 128 + lane * 4]);
            __nv_bfloat162 b0 = *reinterpret_cast<__nv_bfloat162*>(&u.x);
            __nv_bfloat162 b1 = *reinterpret_cast<__nv_bfloat162*>(&u.y);
            float2 f0 = __bfloat1622float2(b0), f1 = __bfloat1622float2(b1);
            float p = f0.x * q4.x + f0.y * q4.y + f1.x * q4.z + f1.y * q4.w;
            p += __shfl_xor_sync(0xffffffffu, p, 1);
            p += __shfl_xor_sync(0xffffffffu, p, 2);

            float4 v4 = *reinterpret_cast<const float4*>(&g_v[(long)s * 128 + lane * 4]);

            float mn = fmaxf(m, p);
            float c = __expf(m - mn);   // first edge: exp(-inf)=0
            float w = __expf(p - mn);
            ssum = ssum * c + w;
            a0 = a0 * c + w * v4.x;
            a1 = a1 * c + w * v4.y;
            a2 = a2 * c + w * v4.z;
            a3 = a3 * c + w * v4.w;
            m = mn;
        }
    }

    float inv = (ssum > 0.f) ? (1.f / ssum) : 0.f;
    float4 fr = *reinterpret_cast<const float4*>(&feat[(long)node * 128 + lane * 4]);
    float x0 = a0 * inv + fr.x;
    float x1 = a1 * inv + fr.y;
    float x2 = a2 * inv + fr.z;
    float x3 = a3 * inv + fr.w;

    // LayerNorm over 128 channels held 4/lane
    float part = x0 + x1 + x2 + x3;
#pragma unroll
    for (int o = 16; o >= 1; o >>= 1) part += __shfl_xor_sync(0xffffffffu, part, o);
    float mu = part * (1.f / 128.f);
    float d0 = x0 - mu, d1 = x1 - mu, d2 = x2 - mu, d3 = x3 - mu;
    float vp = d0 * d0 + d1 * d1 + d2 * d2 + d3 * d3;
#pragma unroll
    for (int o = 16; o >= 1; o >>= 1) vp += __shfl_xor_sync(0xffffffffu, vp, o);
    float rstd = rsqrtf(vp * (1.f / 128.f) + 1e-5f);

    float4 gg = *reinterpret_cast<const float4*>(&ln1g[lane * 4]);
    float4 bb = *reinterpret_cast<const float4*>(&ln1b[lane * 4]);
    float y0 = d0 * rstd * gg.x + bb.x;
    float y1 = d1 * rstd * gg.y + bb.y;
    float y2 = d2 * rstd * gg.z + bb.z;
    float y3 = d3 * rstd * gg.w + bb.w;

    float4 o4 = make_float4(y0, y1, y2, y3);
    *reinterpret_cast<float4*>(&g_rst[(long)node * 128 + lane * 4]) = o4;
    __nv_bfloat162 p0, p1;
    p0.x = __float2bfloat16_rn(y0); p0.y = __float2bfloat16_rn(y1);
    p1.x = __float2bfloat16_rn(y2); p1.y = __float2bfloat16_rn(y3);
    uint2 pk;
    pk.x = *reinterpret_cast<unsigned*>(&p0);
    pk.y = *reinterpret_cast<unsigned*>(&p1);
    *reinterpret_cast<uint2*>(&g_rstbf[(long)node * 128 + lane * 4]) = pk;
}

// ---------------- residual + LayerNorm2 -> output (warp per node) ----------------
__global__ __launch_bounds__(256) void k_ln2(
    const float* __restrict__ ln2g, const float* __restrict__ ln2b,
    float* __restrict__ out, int N)
{
    int gw = (blockIdx.x * blockDim.x + threadIdx.x) >> 5;
    if (gw >= N) return;
    int lane = threadIdx.x & 31;

    float4 r4 = *reinterpret_cast<const float4*>(&g_rst[(long)gw * 128 + lane * 4]);
    float4 f4 = *reinterpret_cast<const float4*>(&g_ffn[(long)gw * 128 + lane * 4]);
    float x0 = r4.x + f4.x, x1 = r4.y + f4.y, x2 = r4.z + f4.z, x3 = r4.w + f4.w;

    float part = x0 + x1 + x2 + x3;
#pragma unroll
    for (int o = 16; o >= 1; o >>= 1) part += __shfl_xor_sync(0xffffffffu, part, o);
    float mu = part * (1.f / 128.f);
    float d0 = x0 - mu, d1 = x1 - mu, d2 = x2 - mu, d3 = x3 - mu;
    float vp = d0 * d0 + d1 * d1 + d2 * d2 + d3 * d3;
#pragma unroll
    for (int o = 16; o >= 1; o >>= 1) vp += __shfl_xor_sync(0xffffffffu, vp, o);
    float rstd = rsqrtf(vp * (1.f / 128.f) + 1e-5f);

    float4 gg = *reinterpret_cast<const float4*>(&ln2g[lane * 4]);
    float4 bb = *reinterpret_cast<const float4*>(&ln2b[lane * 4]);
    float4 o4;
    o4.x = d0 * rstd * gg.x + bb.x;
    o4.y = d1 * rstd * gg.y + bb.y;
    o4.z = d2 * rstd * gg.z + bb.z;
    o4.w = d3 * rstd * gg.w + bb.w;
    *reinterpret_cast<float4*>(&out[(long)gw * 128 + lane * 4]) = o4;
}

// ---------------- launch ----------------
extern "C" void kernel_launch(void* const* d_in, const int* in_sizes, int n_in,
                              void* d_out, int out_size)
{
    const float* feat  = (const float*)d_in[0];
    const int*   src   = (const int*)d_in[1];
    const int*   dst   = (const int*)d_in[2];
    const float* Wq    = (const float*)d_in[3];
    const float* Wk    = (const float*)d_in[4];
    const float* Wv    = (const float*)d_in[5];
    const float* ln1g  = (const float*)d_in[6];
    const float* ln1b  = (const float*)d_in[7];
    const float* ln2g  = (const float*)d_in[8];
    const float* ln2b  = (const float*)d_in[9];
    const float* W1    = (const float*)d_in[10];
    const float* b1    = (const float*)d_in[11];
    const float* prelu = (const float*)d_in[12];
    const float* W2    = (const float*)d_in[13];
    const float* b2    = (const float*)d_in[14];
    float* out = (float*)d_out;

    int N = in_sizes[0] / 128;
    int E = in_sizes[1];

    void *degp, *curp;
    cudaGetSymbolAddress(&degp, g_deg);
    cudaGetSymbolAddress(&curp, g_cursor);
    cudaMemsetAsync(degp, 0, (size_t)N * 4);
    cudaMemsetAsync(curp, 0, (size_t)N * 4);

    // converts
    k_cvt_feat<<<(N * 128 / 4 + 255) / 256, 256>>>(feat, N * 128);
    dim3 gw(64, 5);
    k_cvt_w<<<gw, 256>>>(Wq, Wk, Wv, W1, W2);

    // CSR build
    k_hist<<<(E + 255) / 256, 256>>>(dst, E);
    int nb = (N + 255) / 256;
    k_scan1<<<nb, 256>>>(N);
    k_scan2<<<1, 256>>>(nb);
    k_scan3<<<nb, 256>>>(N);
    k_fill<<<(E + 255) / 256, 256>>>(dst, src, E);

    int mblk = (N + 127) / 128;

    // QKV (bf16 tensor cores)
    dim3 gqkv(3, mblk);
    gemm_qkv<<<gqkv, 256>>>(N);

    // attention + aggregate + residual + LN1 (warp per node)
    k_attn<<<(N * 32 + 255) / 256, 256>>>(feat, ln1g, ln1b, N);

    // FFN
    dim3 gff1(4, mblk);
    gemm_ffn1<<<gff1, 256>>>(N, b1, prelu);
    dim3 gff2(1, mblk);
    gemm_ffn2<<<gff2, 256>>>(N, b2);

    // residual + LN2 -> out (warp per node)
    k_ln2<<<(N * 32 + 255) / 256, 256>>>(ln2g, ln2b, out, N);
}